// round 4
// baseline (speedup 1.0000x reference)
#include <cuda_runtime.h>
#include <cstdint>

// Problem constants (fixed by setup_inputs)
#define B_     16
#define A_     16
#define T_     14
#define S_     1024
#define S2_    512      // estimated (even) subcarriers
#define SYM0   2
#define SYM1   11
#define CHUNK  8        // s2 per block -> 16 output subcarriers -> 16KB contiguous
#define NCHUNK (S2_ / CHUNK)   // 64

// Output (verified R3): real part only, float32, shape (B, R=1, T, S, A, A).
// cov_real[b, s, i, j] = 0.5 * sum_{sym in {2,11}} Re( y[b,i,sym,2*(s>>1)] * conj(y[b,j,sym,2*(s>>1)]) )
// broadcast over t. Each block owns one (b, t, 16-subcarrier) slab = 16KB of
// CONTIGUOUS output, recomputing the (free) covariances locally so every
// block's write stream is a single monotone 16KB burst -> DRAM page locality.
__global__ __launch_bounds__(256, 8)
void cov_stream_kernel(const float* __restrict__ y_real,
                       const float* __restrict__ y_imag,
                       float4*      __restrict__ out4,
                       size_t n4)                     // float4 capacity (fault guard)
{
    __shared__ float2 sv[CHUNK][2][A_];   // [s2_local][pilot][antenna]

    const int bid   = blockIdx.x;
    const int chunk = bid & (NCHUNK - 1);            // 0..63
    const int t     = (bid >> 6) % T_;               // 0..13
    const int b     = bid / (NCHUNK * T_);           // 0..15
    const int tid   = threadIdx.x;

    // ---- gather: 256 threads = 8 s2 x 2 sym x 16 ant ----
    {
        const int a   = tid & (A_ - 1);
        const int k   = (tid >> 4) & 1;
        const int c   = tid >> 5;                    // s2_local 0..7
        const int sym = k ? SYM1 : SYM0;
        const int sc  = 2 * (chunk * CHUNK + c);
        const long off = (((long)(b * A_ + a)) * T_ + sym) * S_ + sc;
        sv[c][k][a] = make_float2(__ldg(y_real + off), __ldg(y_imag + off));
    }
    __syncthreads();

    // ---- compute + stream 4 contiguous-warp float4 stores per thread ----
    // Slab = 16 subcarriers x 256 floats = 4096 floats = 1024 float4.
    // Thread owns q = tid%64 (float4 within one A*A tile), sc0 = tid/64,
    // iterating sc_local = sc0 + 4k. A warp's 32 stores are 512B contiguous.
    const int q  = tid & 63;
    const int i  = q >> 2;
    const int j0 = (q & 3) << 2;
    const int sc0 = tid >> 6;                        // 0..3

    const int sc_base = chunk * (2 * CHUNK);         // first output subcarrier
    const size_t slab = ((size_t)(b * T_ + t) * S_ + sc_base) * 64;

#pragma unroll
    for (int k = 0; k < 4; ++k) {
        const int sc_local = sc0 + 4 * k;            // 0..15
        const int c = sc_local >> 1;                 // s2_local

        const float2 vi0 = sv[c][0][i];
        const float2 vi1 = sv[c][1][i];

        float4 val;
        {
            float2 u = sv[c][0][j0 + 0], w = sv[c][1][j0 + 0];
            val.x = 0.5f * (vi0.x * u.x + vi0.y * u.y + vi1.x * w.x + vi1.y * w.y);
            u = sv[c][0][j0 + 1]; w = sv[c][1][j0 + 1];
            val.y = 0.5f * (vi0.x * u.x + vi0.y * u.y + vi1.x * w.x + vi1.y * w.y);
            u = sv[c][0][j0 + 2]; w = sv[c][1][j0 + 2];
            val.z = 0.5f * (vi0.x * u.x + vi0.y * u.y + vi1.x * w.x + vi1.y * w.y);
            u = sv[c][0][j0 + 3]; w = sv[c][1][j0 + 3];
            val.w = 0.5f * (vi0.x * u.x + vi0.y * u.y + vi1.x * w.x + vi1.y * w.y);
        }

        const size_t idx = slab + (size_t)sc_local * 64 + q;
        if (idx < n4) __stcs(out4 + idx, val);       // evict-first streaming store
    }
}

extern "C" void kernel_launch(void* const* d_in, const int* in_sizes, int n_in,
                              void* d_out, int out_size)
{
    // Identify the two big float arrays (3,670,016 elements each) by size;
    // disambiguate real/imag by input ordering (verified working in R3).
    const float* big[2] = {nullptr, nullptr};
    int nbig = 0;
    for (int i = 0; i < n_in; ++i) {
        if (in_sizes[i] > 100000 && nbig < 2) big[nbig++] = (const float*)d_in[i];
    }

    const float* y_real;
    const float* y_imag;
    if (in_sizes[0] > 100000) {
        y_real = big[0]; y_imag = big[1];   // insertion order (verified)
    } else {
        y_imag = big[0]; y_real = big[1];   // alphabetical order
    }

    cov_stream_kernel<<<B_ * T_ * NCHUNK, 256>>>(y_real, y_imag,
                                                 (float4*)d_out,
                                                 (size_t)out_size / 4);
}

// round 5
// speedup vs baseline: 1.8147x; 1.8147x over previous
#include <cuda_runtime.h>
#include <cstdint>

// Problem constants (fixed by setup_inputs)
#define B_   16
#define A_   16
#define T_   14
#define S_   1024
#define S2_  512       // estimated (even) subcarriers
#define SYM0 2
#define SYM1 11

// Output (verified R3): real part only, float32, shape (B, R=1, T, S, A, A).
// cov_real[b, s, i, j] = 0.5 * sum_{sym in {2,11}} Re( y[b,i,sym,2*(s>>1)] * conj(y[b,j,sym,2*(s>>1)]) )
// broadcast over t (14 copies).
//
// Design (R3 lineage — compute ONCE, broadcast-store):
//   grid = B * S2/2 = 4096 blocks, 256 threads.
//   Each block owns an s2-PAIR -> 4 output subcarrier tiles = 4KB contiguous
//   per t. Threads 0..63 gather the 2x2x16 pilot vectors into smem; each
//   thread computes ONE float4 of the real covariance tile; then 14
//   evict-first streaming stores (one per t), each block burst = 4KB.
__global__ __launch_bounds__(256, 8)
void cov_bcast2_kernel(const float* __restrict__ y_real,
                       const float* __restrict__ y_imag,
                       float4*      __restrict__ out4,
                       size_t n4)                      // float4 capacity (fault guard)
{
    __shared__ float2 sv[2][2][A_];   // [s2_local][pilot][antenna]

    const int bid = blockIdx.x;
    const int b   = bid >> 8;                  // / 256 pairs
    const int p   = bid & 255;                 // s2 pair index: s2 = 2p, 2p+1
    const int tid = threadIdx.x;

    // ---- gather: threads 0..63 load 2 s2 x 2 sym x 16 ant complex ----
    if (tid < 64) {
        const int a   = tid & (A_ - 1);
        const int k   = (tid >> 4) & 1;
        const int c   = tid >> 5;              // s2_local 0/1
        const int sym = k ? SYM1 : SYM0;
        const int sc  = 4 * p + 2 * c;         // even subcarrier 2*(2p+c)
        const long off = (((long)(b * A_ + a)) * T_ + sym) * S_ + sc;
        sv[c][k][a] = make_float2(__ldg(y_real + off), __ldg(y_imag + off));
    }
    __syncthreads();

    // ---- compute ONE float4 (4 adjacent j of real cov) per thread ----
    const int q        = tid & 63;             // float4 within one A*A tile
    const int sc_local = tid >> 6;             // 0..3 -> output sc = 4p + sc_local
    const int c        = sc_local >> 1;        // source s2_local
    const int i        = q >> 2;
    const int j0       = (q & 3) << 2;

    const float2 vi0 = sv[c][0][i];
    const float2 vi1 = sv[c][1][i];

    float4 val;
    {
        float2 u = sv[c][0][j0 + 0], w = sv[c][1][j0 + 0];
        val.x = 0.5f * (vi0.x * u.x + vi0.y * u.y + vi1.x * w.x + vi1.y * w.y);
        u = sv[c][0][j0 + 1]; w = sv[c][1][j0 + 1];
        val.y = 0.5f * (vi0.x * u.x + vi0.y * u.y + vi1.x * w.x + vi1.y * w.y);
        u = sv[c][0][j0 + 2]; w = sv[c][1][j0 + 2];
        val.z = 0.5f * (vi0.x * u.x + vi0.y * u.y + vi1.x * w.x + vi1.y * w.y);
        u = sv[c][0][j0 + 3]; w = sv[c][1][j0 + 3];
        val.w = 0.5f * (vi0.x * u.x + vi0.y * u.y + vi1.x * w.x + vi1.y * w.y);
    }

    // ---- broadcast: 14 streaming stores, 4KB contiguous per block per t ----
    // out float4 index: ((b*T + t)*S + 4p + sc_local) * 64 + q
    size_t idx = ((size_t)(b * T_) * S_ + 4 * (size_t)p + sc_local) * 64 + q;
    const size_t t_stride = (size_t)S_ * 64;

#pragma unroll
    for (int t = 0; t < T_; ++t) {
        if (idx < n4) __stcs(out4 + idx, val);   // evict-first streaming store
        idx += t_stride;
    }
}

extern "C" void kernel_launch(void* const* d_in, const int* in_sizes, int n_in,
                              void* d_out, int out_size)
{
    // Identify the two big float arrays (3,670,016 elements each) by size;
    // disambiguate real/imag by input ordering (verified in R3).
    const float* big[2] = {nullptr, nullptr};
    int nbig = 0;
    for (int i = 0; i < n_in; ++i) {
        if (in_sizes[i] > 100000 && nbig < 2) big[nbig++] = (const float*)d_in[i];
    }

    const float* y_real;
    const float* y_imag;
    if (in_sizes[0] > 100000) {
        y_real = big[0]; y_imag = big[1];   // insertion order (verified)
    } else {
        y_imag = big[0]; y_real = big[1];   // alphabetical order
    }

    cov_bcast2_kernel<<<B_ * (S2_ / 2), 256>>>(y_real, y_imag,
                                               (float4*)d_out,
                                               (size_t)out_size / 4);
}